// round 1
// baseline (speedup 1.0000x reference)
#include <cuda_runtime.h>
#include <math.h>

#define S   1024
#define H   2048
#define NH  16
#define HD  128
#define E   16
#define TOPK 4
#define IM  1408
#define IS  5632
#define EPS 1e-6f

// ---------------- scratch (device globals; no allocations allowed) ----------------
__device__ float g_h1[S*H];
__device__ float g_q[S*H];
__device__ float g_k[S*H];
__device__ float g_v[S*H];
__device__ float g_scores[NH*S*S];          // 64 MB
__device__ float g_attn[S*H];
__device__ float g_attno[S*H];
__device__ float g_x2[S*H];
__device__ float g_h2[S*H];
__device__ float g_gs[S*IS];
__device__ float g_us[S*IS];
__device__ float g_shared[S*H];
__device__ float g_logits[S*E];
__device__ float g_sg[S];
__device__ int   g_cnt[E];
__device__ int   g_tk_e[S*TOPK];
__device__ int   g_tk_slot[S*TOPK];
__device__ float g_tk_w[S*TOPK];
__device__ float g_hbuf[E*S*H];             // 128 MB (per-expert gathered tokens)
__device__ float g_gbuf[E*S*IM];            // 92 MB
__device__ float g_ubuf[E*S*IM];            // 92 MB
__device__ float g_ybuf[E*S*H];             // 128 MB

// ---------------- block reductions ----------------
__device__ __forceinline__ float blockReduceSum(float v) {
    __shared__ float sh[33];
    int lane = threadIdx.x & 31, wid = threadIdx.x >> 5;
    #pragma unroll
    for (int o = 16; o; o >>= 1) v += __shfl_down_sync(0xffffffffu, v, o);
    if (lane == 0) sh[wid] = v;
    __syncthreads();
    int nw = (blockDim.x + 31) >> 5;
    float t = (threadIdx.x < nw) ? sh[threadIdx.x] : 0.f;
    if (wid == 0) {
        #pragma unroll
        for (int o = 16; o; o >>= 1) t += __shfl_down_sync(0xffffffffu, t, o);
        if (lane == 0) sh[32] = t;
    }
    __syncthreads();
    float r = sh[32];
    __syncthreads();
    return r;
}

__device__ __forceinline__ float blockReduceMax(float v) {
    __shared__ float sh[33];
    int lane = threadIdx.x & 31, wid = threadIdx.x >> 5;
    #pragma unroll
    for (int o = 16; o; o >>= 1) v = fmaxf(v, __shfl_down_sync(0xffffffffu, v, o));
    if (lane == 0) sh[wid] = v;
    __syncthreads();
    int nw = (blockDim.x + 31) >> 5;
    float t = (threadIdx.x < nw) ? sh[threadIdx.x] : -3.4e38f;
    if (wid == 0) {
        #pragma unroll
        for (int o = 16; o; o >>= 1) t = fmaxf(t, __shfl_down_sync(0xffffffffu, t, o));
        if (lane == 0) sh[32] = t;
    }
    __syncthreads();
    float r = sh[32];
    __syncthreads();
    return r;
}

// ---------------- generic batched SGEMM: C = alpha*A@B(+bias) ----------------
// A: [M,K] row-major (lda), B: [K,N] row-major (ldb) or [N,K] if transB,
// C: [M,N] (ldc). Per-batch strides sA/sB/sC (in elements). If mcnt != null,
// effective M for batch b is mcnt[b] (sparse MoE). K must be a multiple of 8,
// all leading dims multiples of 4 (true for every call site here).
__global__ void __launch_bounds__(256)
sgemm_kernel(const float* __restrict__ A, const float* __restrict__ B,
             const float* __restrict__ bias, float* __restrict__ C,
             int M, int N, int K, int lda, int ldb, int ldc,
             long long sA, long long sB, long long sC,
             float alpha, int transB, const int* __restrict__ mcnt)
{
    const int b = blockIdx.z;
    if (mcnt) M = mcnt[b];
    const int m0 = blockIdx.y * 128;
    if (m0 >= M) return;
    const int n0 = blockIdx.x * 128;

    const float* Ab = A + (long long)b * sA;
    const float* Bb = B + (long long)b * sB;
    float*       Cb = C + (long long)b * sC;

    __shared__ float As[8][128];
    __shared__ float Bs[8][128];

    const int tid = threadIdx.x;
    const int tx  = tid & 15;
    const int ty  = tid >> 4;

    const int arow = tid >> 1;           // 0..127 (also N-row for transB loads)
    const int akq  = (tid & 1) * 4;      // 0 or 4
    const int bk   = tid >> 5;           // 0..7
    const int bn   = (tid & 31) * 4;     // 0..124

    float acc[8][8];
    #pragma unroll
    for (int i = 0; i < 8; i++)
        #pragma unroll
        for (int j = 0; j < 8; j++) acc[i][j] = 0.f;

    for (int k0 = 0; k0 < K; k0 += 8) {
        float4 av = make_float4(0.f, 0.f, 0.f, 0.f);
        if (m0 + arow < M)
            av = *reinterpret_cast<const float4*>(&Ab[(long long)(m0 + arow) * lda + k0 + akq]);
        float4 bv = make_float4(0.f, 0.f, 0.f, 0.f);
        if (!transB) {
            if (n0 + bn < N)
                bv = *reinterpret_cast<const float4*>(&Bb[(long long)(k0 + bk) * ldb + n0 + bn]);
        } else {
            if (n0 + arow < N)
                bv = *reinterpret_cast<const float4*>(&Bb[(long long)(n0 + arow) * ldb + k0 + akq]);
        }
        __syncthreads();   // previous iteration's compute done before overwrite
        As[akq + 0][arow] = av.x; As[akq + 1][arow] = av.y;
        As[akq + 2][arow] = av.z; As[akq + 3][arow] = av.w;
        if (!transB) {
            *reinterpret_cast<float4*>(&Bs[bk][bn]) = bv;
        } else {
            Bs[akq + 0][arow] = bv.x; Bs[akq + 1][arow] = bv.y;
            Bs[akq + 2][arow] = bv.z; Bs[akq + 3][arow] = bv.w;
        }
        __syncthreads();
        #pragma unroll
        for (int kk = 0; kk < 8; kk++) {
            float4 a0 = *reinterpret_cast<const float4*>(&As[kk][ty * 8]);
            float4 a1 = *reinterpret_cast<const float4*>(&As[kk][ty * 8 + 4]);
            float4 b0 = *reinterpret_cast<const float4*>(&Bs[kk][tx * 8]);
            float4 b1 = *reinterpret_cast<const float4*>(&Bs[kk][tx * 8 + 4]);
            float a[8] = {a0.x, a0.y, a0.z, a0.w, a1.x, a1.y, a1.z, a1.w};
            float bb[8] = {b0.x, b0.y, b0.z, b0.w, b1.x, b1.y, b1.z, b1.w};
            #pragma unroll
            for (int i = 0; i < 8; i++)
                #pragma unroll
                for (int j = 0; j < 8; j++) acc[i][j] += a[i] * bb[j];
        }
    }

    #pragma unroll
    for (int i = 0; i < 8; i++) {
        int gm = m0 + ty * 8 + i;
        if (gm >= M) continue;
        #pragma unroll
        for (int j = 0; j < 8; j++) {
            int gn = n0 + tx * 8 + j;
            if (gn < N) {
                float v = acc[i][j] * alpha;
                if (bias) v += bias[gn];
                Cb[(long long)gm * ldc + gn] = v;
            }
        }
    }
}

// ---------------- elementwise / norm / attention helpers ----------------
__global__ void rmsnorm_kernel(const float* __restrict__ x, const float* __restrict__ w,
                               float* __restrict__ y) {
    int t = blockIdx.x;
    const float* xr = x + (long long)t * H;
    float s = 0.f;
    for (int i = threadIdx.x; i < H; i += blockDim.x) { float v = xr[i]; s += v * v; }
    s = blockReduceSum(s);
    float scale = rsqrtf(s / (float)H + EPS);
    float* yr = y + (long long)t * H;
    for (int i = threadIdx.x; i < H; i += blockDim.x) yr[i] = xr[i] * scale * w[i];
}

__global__ void rope_kernel(const int* __restrict__ pos, float* __restrict__ q,
                            float* __restrict__ k) {
    int t = blockIdx.x;
    int h = threadIdx.x >> 6;   // 16 heads
    int d = threadIdx.x & 63;   // half of head dim
    float p = (float)pos[t];
    float inv = powf(1.0e6f, -(float)d * (1.0f / 64.0f));
    float ang = p * inv;
    float sn, cs;
    sincosf(ang, &sn, &cs);
    long long base = (long long)t * H + h * HD;
    float x1 = q[base + d], x2 = q[base + 64 + d];
    q[base + d]      = x1 * cs - x2 * sn;
    q[base + 64 + d] = x2 * cs + x1 * sn;
    x1 = k[base + d]; x2 = k[base + 64 + d];
    k[base + d]      = x1 * cs - x2 * sn;
    k[base + 64 + d] = x2 * cs + x1 * sn;
}

__global__ void softmax_causal_kernel(float* __restrict__ scores) {
    int r = blockIdx.x, h = blockIdx.y;
    float* row = scores + ((long long)h * S + r) * (long long)S;
    int len = r + 1;
    float m = -3.4e38f;
    for (int i = threadIdx.x; i < len; i += blockDim.x) m = fmaxf(m, row[i]);
    m = blockReduceMax(m);
    float s = 0.f;
    for (int i = threadIdx.x; i < len; i += blockDim.x) {
        float e = expf(row[i] - m);
        row[i] = e; s += e;
    }
    s = blockReduceSum(s);
    float inv = 1.f / s;
    for (int i = threadIdx.x; i < len; i += blockDim.x) row[i] *= inv;
    for (int i = len + threadIdx.x; i < S; i += blockDim.x) row[i] = 0.f;
}

__global__ void add_kernel(const float* __restrict__ a, const float* __restrict__ b,
                           float* __restrict__ c, int n) {
    int i = blockIdx.x * blockDim.x + threadIdx.x;
    if (i < n) c[i] = a[i] + b[i];
}

__global__ void silumul_kernel(float* __restrict__ g, const float* __restrict__ u, int n) {
    int i = blockIdx.x * blockDim.x + threadIdx.x;
    if (i < n) { float x = g[i]; g[i] = (x / (1.f + expf(-x))) * u[i]; }
}

__global__ void sgate_kernel(const float* __restrict__ h2, const float* __restrict__ wsg,
                             float* __restrict__ sg) {
    int t = blockIdx.x;
    float s = 0.f;
    for (int i = threadIdx.x; i < H; i += blockDim.x) s += h2[(long long)t * H + i] * wsg[i];
    s = blockReduceSum(s);
    if (threadIdx.x == 0) sg[t] = 1.f / (1.f + expf(-s));
}

// ---------------- MoE routing ----------------
__global__ void zero_cnt_kernel(int* cnt) { if (threadIdx.x < E) cnt[threadIdx.x] = 0; }

__global__ void routing_kernel(const float* __restrict__ logits, int* __restrict__ cnt,
                               int* __restrict__ tke, int* __restrict__ tks,
                               float* __restrict__ tkw) {
    int t = blockIdx.x * blockDim.x + threadIdx.x;
    if (t >= S) return;
    float p[E];
    float mx = -3.4e38f;
    #pragma unroll
    for (int e = 0; e < E; e++) { p[e] = logits[t * E + e]; mx = fmaxf(mx, p[e]); }
    float sum = 0.f;
    #pragma unroll
    for (int e = 0; e < E; e++) { p[e] = expf(p[e] - mx); sum += p[e]; }
    float inv = 1.f / sum;
    #pragma unroll
    for (int e = 0; e < E; e++) p[e] *= inv;
    int ids[TOPK]; float ws[TOPK]; float wsum = 0.f;
    #pragma unroll
    for (int k = 0; k < TOPK; k++) {
        float bv = -1.f; int bi = 0;
        #pragma unroll
        for (int e = 0; e < E; e++) if (p[e] > bv) { bv = p[e]; bi = e; }
        ids[k] = bi; ws[k] = bv; wsum += bv; p[bi] = -2.f;
    }
    float wi = 1.f / wsum;
    #pragma unroll
    for (int k = 0; k < TOPK; k++) {
        int slot = atomicAdd(&cnt[ids[k]], 1);
        tke[t * TOPK + k] = ids[k];
        tks[t * TOPK + k] = slot;
        tkw[t * TOPK + k] = ws[k] * wi;
    }
}

__global__ void gather_kernel(const float* __restrict__ h2, const int* __restrict__ tke,
                              const int* __restrict__ tks, float* __restrict__ hbuf) {
    int idx = blockIdx.x;            // 0 .. S*TOPK-1
    int t = idx >> 2;
    int e = tke[idx], slot = tks[idx];
    const float4* src = reinterpret_cast<const float4*>(h2 + (long long)t * H);
    float4* dst = reinterpret_cast<float4*>(hbuf + ((long long)e * S + slot) * H);
    for (int i = threadIdx.x; i < H / 4; i += blockDim.x) dst[i] = src[i];
}

__global__ void silumul_expert_kernel(float* __restrict__ gbuf, const float* __restrict__ ubuf,
                                      const int* __restrict__ cnt) {
    int e = blockIdx.y, slot = blockIdx.x;
    if (slot >= cnt[e]) return;
    long long base = ((long long)e * S + slot) * IM;
    for (int i = threadIdx.x; i < IM; i += blockDim.x) {
        float x = gbuf[base + i];
        gbuf[base + i] = (x / (1.f + expf(-x))) * ubuf[base + i];
    }
}

__global__ void combine_kernel(const float* __restrict__ shrd, const float* __restrict__ sg,
                               const float* __restrict__ ybuf,
                               const int* __restrict__ tke, const int* __restrict__ tks,
                               const float* __restrict__ tkw, float* __restrict__ out) {
    int t = blockIdx.x;
    float g = sg[t];
    int e0 = tke[t*4+0], e1 = tke[t*4+1], e2 = tke[t*4+2], e3 = tke[t*4+3];
    int s0 = tks[t*4+0], s1 = tks[t*4+1], s2 = tks[t*4+2], s3 = tks[t*4+3];
    float w0 = tkw[t*4+0], w1 = tkw[t*4+1], w2 = tkw[t*4+2], w3 = tkw[t*4+3];
    const float* y0 = ybuf + ((long long)e0 * S + s0) * H;
    const float* y1 = ybuf + ((long long)e1 * S + s1) * H;
    const float* y2 = ybuf + ((long long)e2 * S + s2) * H;
    const float* y3 = ybuf + ((long long)e3 * S + s3) * H;
    const float* sh = shrd + (long long)t * H;
    float* o = out + (long long)t * H;
    for (int i = threadIdx.x; i < H; i += blockDim.x)
        o[i] = g * sh[i] + w0 * y0[i] + w1 * y1[i] + w2 * y2[i] + w3 * y3[i];
}

// ---------------- host orchestration ----------------
static inline void gemm(const float* A, const float* B, const float* bias, float* C,
                        int M, int N, int K, int lda, int ldb, int ldc,
                        long long sA, long long sB, long long sC,
                        float alpha, int transB, const int* mcnt, int batch) {
    dim3 grid((N + 127) / 128, (M + 127) / 128, batch);
    sgemm_kernel<<<grid, 256>>>(A, B, bias, C, M, N, K, lda, ldb, ldc,
                                sA, sB, sC, alpha, transB, mcnt);
}

extern "C" void kernel_launch(void* const* d_in, const int* in_sizes, int n_in,
                              void* d_out, int out_size) {
    const int*   positions = (const int*)  d_in[0];
    const float* hidden    = (const float*)d_in[1];
    const float* ln1       = (const float*)d_in[2];
    const float* ln2       = (const float*)d_in[3];
    const float* q_w       = (const float*)d_in[4];
    const float* q_b       = (const float*)d_in[5];
    const float* k_w       = (const float*)d_in[6];
    const float* k_b       = (const float*)d_in[7];
    const float* v_w       = (const float*)d_in[8];
    const float* v_b       = (const float*)d_in[9];
    const float* o_w       = (const float*)d_in[10];
    const float* router_w  = (const float*)d_in[11];
    const float* we_gate   = (const float*)d_in[12];
    const float* we_up     = (const float*)d_in[13];
    const float* we_down   = (const float*)d_in[14];
    const float* ws_gate   = (const float*)d_in[15];
    const float* ws_up     = (const float*)d_in[16];
    const float* ws_down   = (const float*)d_in[17];
    const float* wsg       = (const float*)d_in[18];
    float* out = (float*)d_out;

    float *h1, *q, *k, *v, *scores, *attn, *attno, *x2, *h2, *gs, *us, *shrd;
    float *logits, *sgv, *hbuf, *gbuf, *ubuf, *ybuf, *tkw;
    int *cnt, *tke, *tks;
    cudaGetSymbolAddress((void**)&h1,     g_h1);
    cudaGetSymbolAddress((void**)&q,      g_q);
    cudaGetSymbolAddress((void**)&k,      g_k);
    cudaGetSymbolAddress((void**)&v,      g_v);
    cudaGetSymbolAddress((void**)&scores, g_scores);
    cudaGetSymbolAddress((void**)&attn,   g_attn);
    cudaGetSymbolAddress((void**)&attno,  g_attno);
    cudaGetSymbolAddress((void**)&x2,     g_x2);
    cudaGetSymbolAddress((void**)&h2,     g_h2);
    cudaGetSymbolAddress((void**)&gs,     g_gs);
    cudaGetSymbolAddress((void**)&us,     g_us);
    cudaGetSymbolAddress((void**)&shrd,   g_shared);
    cudaGetSymbolAddress((void**)&logits, g_logits);
    cudaGetSymbolAddress((void**)&sgv,    g_sg);
    cudaGetSymbolAddress((void**)&cnt,    g_cnt);
    cudaGetSymbolAddress((void**)&tke,    g_tk_e);
    cudaGetSymbolAddress((void**)&tks,    g_tk_slot);
    cudaGetSymbolAddress((void**)&tkw,    g_tk_w);
    cudaGetSymbolAddress((void**)&hbuf,   g_hbuf);
    cudaGetSymbolAddress((void**)&gbuf,   g_gbuf);
    cudaGetSymbolAddress((void**)&ubuf,   g_ubuf);
    cudaGetSymbolAddress((void**)&ybuf,   g_ybuf);

    // --- pre-attention norm + QKV + RoPE ---
    rmsnorm_kernel<<<S, 256>>>(hidden, ln1, h1);
    gemm(h1, q_w, q_b, q, S, H, H, H, H, H, 0, 0, 0, 1.f, 0, nullptr, 1);
    gemm(h1, k_w, k_b, k, S, H, H, H, H, H, 0, 0, 0, 1.f, 0, nullptr, 1);
    gemm(h1, v_w, v_b, v, S, H, H, H, H, H, 0, 0, 0, 1.f, 0, nullptr, 1);
    rope_kernel<<<S, 1024>>>(positions, q, k);

    // --- attention: scores = Q K^T / sqrt(HD) (batched over heads), causal softmax, PV ---
    gemm(q, k, nullptr, scores, S, S, HD, H, H, S,
         HD, HD, (long long)S * S, 0.08838834764831845f, 1, nullptr, NH);
    softmax_causal_kernel<<<dim3(S, NH), 256>>>(scores);
    gemm(scores, v, nullptr, attn, S, HD, S, S, H, H,
         (long long)S * S, HD, HD, 1.f, 0, nullptr, NH);
    gemm(attn, o_w, nullptr, attno, S, H, H, H, H, H, 0, 0, 0, 1.f, 0, nullptr, 1);
    add_kernel<<<(S * H + 255) / 256, 256>>>(attno, hidden, x2, S * H);

    // --- post-attention norm ---
    rmsnorm_kernel<<<S, 256>>>(x2, ln2, h2);

    // --- shared expert ---
    gemm(h2, ws_gate, nullptr, gs, S, IS, H, H, IS, IS, 0, 0, 0, 1.f, 0, nullptr, 1);
    gemm(h2, ws_up,   nullptr, us, S, IS, H, H, IS, IS, 0, 0, 0, 1.f, 0, nullptr, 1);
    silumul_kernel<<<(S * IS + 255) / 256, 256>>>(gs, us, S * IS);
    gemm(gs, ws_down, nullptr, shrd, S, H, IS, IS, H, H, 0, 0, 0, 1.f, 0, nullptr, 1);
    sgate_kernel<<<S, 256>>>(h2, wsg, sgv);

    // --- router + sparse expert dispatch ---
    gemm(h2, router_w, nullptr, logits, S, E, H, H, E, E, 0, 0, 0, 1.f, 0, nullptr, 1);
    zero_cnt_kernel<<<1, 32>>>(cnt);
    routing_kernel<<<(S + 255) / 256, 256>>>(logits, cnt, tke, tks, tkw);
    gather_kernel<<<S * TOPK, 256>>>(h2, tke, tks, hbuf);

    // --- expert MLPs: batched over experts with per-expert row counts ---
    gemm(hbuf, we_gate, nullptr, gbuf, S, IM, H, H, IM, IM,
         (long long)S * H, (long long)H * IM, (long long)S * IM, 1.f, 0, cnt, E);
    gemm(hbuf, we_up,   nullptr, ubuf, S, IM, H, H, IM, IM,
         (long long)S * H, (long long)H * IM, (long long)S * IM, 1.f, 0, cnt, E);
    silumul_expert_kernel<<<dim3(S, E), 256>>>(gbuf, ubuf, cnt);
    gemm(gbuf, we_down, nullptr, ybuf, S, H, IM, IM, H, H,
         (long long)S * IM, (long long)IM * H, (long long)S * H, 1.f, 0, cnt, E);

    // --- final combine: out = sigmoid_gate*shared + sum_k w_k * y_expert_k ---
    combine_kernel<<<S, 256>>>(shrd, sgv, ybuf, tke, tks, tkw, out);
}

// round 2
// speedup vs baseline: 3.3202x; 3.3202x over previous
#include <cuda_runtime.h>
#include <math.h>
#include <stdint.h>

#define S   1024
#define H   2048
#define NH  16
#define HD  128
#define E   16
#define TOPK 4
#define IM  1408
#define IS  5632
#define EPS 1e-6f

// ---------------- scratch (device globals; no allocations allowed) ----------------
__device__ float g_h1[S*H];
__device__ float g_q[S*H];
__device__ float g_k[S*H];
__device__ float g_v[S*H];
__device__ float g_scores[NH*S*S];          // 64 MB
__device__ float g_attn[S*H];
__device__ float g_attno[S*H];
__device__ float g_x2[S*H];
__device__ float g_h2[S*H];
__device__ float g_gs[S*IS];
__device__ float g_us[S*IS];
__device__ float g_shared[S*H];
__device__ float g_logits[S*E];
__device__ float g_sg[S];
__device__ int   g_cnt[E];
__device__ int   g_tk_e[S*TOPK];
__device__ int   g_tk_slot[S*TOPK];
__device__ float g_tk_w[S*TOPK];
__device__ float g_hbuf[E*S*H];
__device__ float g_gbuf[E*S*IM];
__device__ float g_ubuf[E*S*IM];
__device__ float g_ybuf[E*S*H];

// ---------------- block reductions ----------------
__device__ __forceinline__ float blockReduceSum(float v) {
    __shared__ float sh[33];
    int lane = threadIdx.x & 31, wid = threadIdx.x >> 5;
    #pragma unroll
    for (int o = 16; o; o >>= 1) v += __shfl_down_sync(0xffffffffu, v, o);
    if (lane == 0) sh[wid] = v;
    __syncthreads();
    int nw = (blockDim.x + 31) >> 5;
    float t = (threadIdx.x < nw) ? sh[threadIdx.x] : 0.f;
    if (wid == 0) {
        #pragma unroll
        for (int o = 16; o; o >>= 1) t += __shfl_down_sync(0xffffffffu, t, o);
        if (lane == 0) sh[32] = t;
    }
    __syncthreads();
    float r = sh[32];
    __syncthreads();
    return r;
}

__device__ __forceinline__ float blockReduceMax(float v) {
    __shared__ float sh[33];
    int lane = threadIdx.x & 31, wid = threadIdx.x >> 5;
    #pragma unroll
    for (int o = 16; o; o >>= 1) v = fmaxf(v, __shfl_down_sync(0xffffffffu, v, o));
    if (lane == 0) sh[wid] = v;
    __syncthreads();
    int nw = (blockDim.x + 31) >> 5;
    float t = (threadIdx.x < nw) ? sh[threadIdx.x] : -3.4e38f;
    if (wid == 0) {
        #pragma unroll
        for (int o = 16; o; o >>= 1) t = fmaxf(t, __shfl_down_sync(0xffffffffu, t, o));
        if (lane == 0) sh[32] = t;
    }
    __syncthreads();
    float r = sh[32];
    __syncthreads();
    return r;
}

// ---------------- TF32 tensor-core batched GEMM ----------------
// C = alpha * A @ B (+bias). A:[M,K] row-major. B:[K,N] row-major, or [N,K] if transB.
// Per-batch element strides sA/sB/sC. mcnt: per-batch effective M (sparse MoE).
// Requirements (all call sites satisfy): K%16==0, lda/ldb/ldc%4==0.
__device__ __forceinline__ uint32_t f2tf32(float f) {
    uint32_t r;
    asm("cvt.rna.tf32.f32 %0, %1;" : "=r"(r) : "f"(f));
    return r;
}

__device__ __forceinline__ void mma_tf32(float& d0, float& d1, float& d2, float& d3,
                                         uint32_t a0, uint32_t a1, uint32_t a2, uint32_t a3,
                                         uint32_t b0, uint32_t b1) {
    asm volatile(
        "mma.sync.aligned.m16n8k8.row.col.f32.tf32.tf32.f32 "
        "{%0,%1,%2,%3}, {%4,%5,%6,%7}, {%8,%9}, {%0,%1,%2,%3};"
        : "+f"(d0), "+f"(d1), "+f"(d2), "+f"(d3)
        : "r"(a0), "r"(a1), "r"(a2), "r"(a3), "r"(b0), "r"(b1));
}

#define LDA_SH 20    // padded row length for [128][.] m-major tiles
#define LDB_SH 136   // padded row length for [16][.] k-major B tiles

__global__ void __launch_bounds__(256)
tgemm_kernel(const float* __restrict__ A, const float* __restrict__ B,
             const float* __restrict__ bias, float* __restrict__ C,
             int M, int N, int K, int lda, int ldb, int ldc,
             long long sA, long long sB, long long sC,
             float alpha, int transB, const int* __restrict__ mcnt)
{
    const int b = blockIdx.z;
    if (mcnt) M = mcnt[b];
    const int m0 = blockIdx.y * 128;
    if (m0 >= M) return;
    const int n0 = blockIdx.x * 128;

    const float* Ab = A + (long long)b * sA;
    const float* Bb = B + (long long)b * sB;
    float*       Cb = C + (long long)b * sC;

    __shared__ uint32_t As[128 * LDA_SH];   // tf32, [m][k] layout
    __shared__ uint32_t Bs[128 * LDA_SH];   // tf32, [k][n] (pad 136) or [n][k] (pad 20)

    const int tid  = threadIdx.x;
    const int lane = tid & 31;
    const int warp = tid >> 5;
    const int wm   = (warp & 3) * 32;   // warp row base in tile
    const int wn   = (warp >> 2) * 64;  // warp col base in tile
    const int g    = lane >> 2;         // groupID
    const int tg   = lane & 3;          // thread-in-group

    // gmem load mapping
    const int arow = tid >> 2;          // 0..63 (plus +64 second pass)
    const int acq  = (tid & 3) * 4;     // k offset (quad)
    const int brow = tid >> 5;          // 0..7 (plus +8)
    const int bn4  = (tid & 31) * 4;    // n offset (quad)

    float acc[2][8][4];
    #pragma unroll
    for (int i = 0; i < 2; i++)
        #pragma unroll
        for (int j = 0; j < 8; j++)
            #pragma unroll
            for (int c = 0; c < 4; c++) acc[i][j][c] = 0.f;

    float4 avr[2], bvr[2];
    const float4 zf4 = make_float4(0.f, 0.f, 0.f, 0.f);

    // --- prefetch tile 0 ---
    {
        #pragma unroll
        for (int p = 0; p < 2; p++) {
            int r = arow + p * 64;
            avr[p] = (m0 + r < M)
                ? *reinterpret_cast<const float4*>(&Ab[(long long)(m0 + r) * lda + acq]) : zf4;
        }
        if (!transB) {
            #pragma unroll
            for (int p = 0; p < 2; p++) {
                int k = brow + p * 8;
                bvr[p] = (n0 + bn4 < N)
                    ? *reinterpret_cast<const float4*>(&Bb[(long long)k * ldb + n0 + bn4]) : zf4;
            }
        } else {
            #pragma unroll
            for (int p = 0; p < 2; p++) {
                int r = arow + p * 64;
                bvr[p] = (n0 + r < N)
                    ? *reinterpret_cast<const float4*>(&Bb[(long long)(n0 + r) * ldb + acq]) : zf4;
            }
        }
    }

    for (int kt = 0; kt < K; kt += 16) {
        __syncthreads();
        // store prefetched regs -> smem (tf32)
        #pragma unroll
        for (int p = 0; p < 2; p++) {
            int r = arow + p * 64;
            uint32_t* d = &As[r * LDA_SH + acq];
            d[0] = f2tf32(avr[p].x); d[1] = f2tf32(avr[p].y);
            d[2] = f2tf32(avr[p].z); d[3] = f2tf32(avr[p].w);
        }
        if (!transB) {
            #pragma unroll
            for (int p = 0; p < 2; p++) {
                int k = brow + p * 8;
                uint32_t* d = &Bs[k * LDB_SH + bn4];
                d[0] = f2tf32(bvr[p].x); d[1] = f2tf32(bvr[p].y);
                d[2] = f2tf32(bvr[p].z); d[3] = f2tf32(bvr[p].w);
            }
        } else {
            #pragma unroll
            for (int p = 0; p < 2; p++) {
                int r = arow + p * 64;
                uint32_t* d = &Bs[r * LDA_SH + acq];
                d[0] = f2tf32(bvr[p].x); d[1] = f2tf32(bvr[p].y);
                d[2] = f2tf32(bvr[p].z); d[3] = f2tf32(bvr[p].w);
            }
        }
        __syncthreads();

        // prefetch next tile
        if (kt + 16 < K) {
            int kn = kt + 16;
            #pragma unroll
            for (int p = 0; p < 2; p++) {
                int r = arow + p * 64;
                avr[p] = (m0 + r < M)
                    ? *reinterpret_cast<const float4*>(&Ab[(long long)(m0 + r) * lda + kn + acq]) : zf4;
            }
            if (!transB) {
                #pragma unroll
                for (int p = 0; p < 2; p++) {
                    int k = brow + p * 8;
                    bvr[p] = (n0 + bn4 < N)
                        ? *reinterpret_cast<const float4*>(&Bb[(long long)(kn + k) * ldb + n0 + bn4]) : zf4;
                }
            } else {
                #pragma unroll
                for (int p = 0; p < 2; p++) {
                    int r = arow + p * 64;
                    bvr[p] = (n0 + r < N)
                        ? *reinterpret_cast<const float4*>(&Bb[(long long)(n0 + r) * ldb + kn + acq]) : zf4;
                }
            }
        }

        // compute: 2 k8-steps, 2 m16 x 8 n8 mma per step
        #pragma unroll
        for (int kk = 0; kk < 16; kk += 8) {
            uint32_t af[2][4];
            #pragma unroll
            for (int mt = 0; mt < 2; mt++) {
                const uint32_t* base = &As[(wm + mt * 16 + g) * LDA_SH + kk + tg];
                af[mt][0] = base[0];
                af[mt][1] = base[8 * LDA_SH];
                af[mt][2] = base[4];
                af[mt][3] = base[8 * LDA_SH + 4];
            }
            uint32_t bf[8][2];
            if (!transB) {
                #pragma unroll
                for (int nt = 0; nt < 8; nt++) {
                    int n = wn + nt * 8 + g;
                    bf[nt][0] = Bs[(kk + tg) * LDB_SH + n];
                    bf[nt][1] = Bs[(kk + tg + 4) * LDB_SH + n];
                }
            } else {
                #pragma unroll
                for (int nt = 0; nt < 8; nt++) {
                    int n = wn + nt * 8 + g;
                    bf[nt][0] = Bs[n * LDA_SH + kk + tg];
                    bf[nt][1] = Bs[n * LDA_SH + kk + tg + 4];
                }
            }
            #pragma unroll
            for (int mt = 0; mt < 2; mt++)
                #pragma unroll
                for (int nt = 0; nt < 8; nt++)
                    mma_tf32(acc[mt][nt][0], acc[mt][nt][1], acc[mt][nt][2], acc[mt][nt][3],
                             af[mt][0], af[mt][1], af[mt][2], af[mt][3],
                             bf[nt][0], bf[nt][1]);
        }
    }

    // epilogue
    #pragma unroll
    for (int mt = 0; mt < 2; mt++) {
        int r0 = m0 + wm + mt * 16 + g;
        int r1 = r0 + 8;
        #pragma unroll
        for (int nt = 0; nt < 8; nt++) {
            int col = n0 + wn + nt * 8 + 2 * tg;
            if (col >= N) continue;
            float b0 = bias ? bias[col]     : 0.f;
            float b1 = bias ? bias[col + 1] : 0.f;
            if (r0 < M) {
                float2 v = make_float2(acc[mt][nt][0] * alpha + b0,
                                       acc[mt][nt][1] * alpha + b1);
                *reinterpret_cast<float2*>(&Cb[(long long)r0 * ldc + col]) = v;
            }
            if (r1 < M) {
                float2 v = make_float2(acc[mt][nt][2] * alpha + b0,
                                       acc[mt][nt][3] * alpha + b1);
                *reinterpret_cast<float2*>(&Cb[(long long)r1 * ldc + col]) = v;
            }
        }
    }
}

// ---------------- elementwise / norm / attention helpers ----------------
__global__ void rmsnorm_kernel(const float* __restrict__ x, const float* __restrict__ w,
                               float* __restrict__ y) {
    int t = blockIdx.x;
    const float* xr = x + (long long)t * H;
    float s = 0.f;
    for (int i = threadIdx.x; i < H; i += blockDim.x) { float v = xr[i]; s += v * v; }
    s = blockReduceSum(s);
    float scale = rsqrtf(s / (float)H + EPS);
    float* yr = y + (long long)t * H;
    for (int i = threadIdx.x; i < H; i += blockDim.x) yr[i] = xr[i] * scale * w[i];
}

__global__ void rope_kernel(const int* __restrict__ pos, float* __restrict__ q,
                            float* __restrict__ k) {
    int t = blockIdx.x;
    int h = threadIdx.x >> 6;
    int d = threadIdx.x & 63;
    float p = (float)pos[t];
    float inv = powf(1.0e6f, -(float)d * (1.0f / 64.0f));
    float ang = p * inv;
    float sn, cs;
    sincosf(ang, &sn, &cs);
    long long base = (long long)t * H + h * HD;
    float x1 = q[base + d], x2 = q[base + 64 + d];
    q[base + d]      = x1 * cs - x2 * sn;
    q[base + 64 + d] = x2 * cs + x1 * sn;
    x1 = k[base + d]; x2 = k[base + 64 + d];
    k[base + d]      = x1 * cs - x2 * sn;
    k[base + 64 + d] = x2 * cs + x1 * sn;
}

__global__ void softmax_causal_kernel(float* __restrict__ scores) {
    int r = blockIdx.x, h = blockIdx.y;
    float* row = scores + ((long long)h * S + r) * (long long)S;
    int len = r + 1;
    float m = -3.4e38f;
    for (int i = threadIdx.x; i < len; i += blockDim.x) m = fmaxf(m, row[i]);
    m = blockReduceMax(m);
    float s = 0.f;
    for (int i = threadIdx.x; i < len; i += blockDim.x) {
        float e = expf(row[i] - m);
        row[i] = e; s += e;
    }
    s = blockReduceSum(s);
    float inv = 1.f / s;
    for (int i = threadIdx.x; i < len; i += blockDim.x) row[i] *= inv;
    for (int i = len + threadIdx.x; i < S; i += blockDim.x) row[i] = 0.f;
}

__global__ void add_kernel(const float* __restrict__ a, const float* __restrict__ b,
                           float* __restrict__ c, int n) {
    int i = blockIdx.x * blockDim.x + threadIdx.x;
    if (i < n) c[i] = a[i] + b[i];
}

__global__ void silumul_kernel(float* __restrict__ g, const float* __restrict__ u, int n) {
    int i = blockIdx.x * blockDim.x + threadIdx.x;
    if (i < n) { float x = g[i]; g[i] = (x / (1.f + expf(-x))) * u[i]; }
}

__global__ void sgate_kernel(const float* __restrict__ h2, const float* __restrict__ wsg,
                             float* __restrict__ sg) {
    int t = blockIdx.x;
    float s = 0.f;
    for (int i = threadIdx.x; i < H; i += blockDim.x) s += h2[(long long)t * H + i] * wsg[i];
    s = blockReduceSum(s);
    if (threadIdx.x == 0) sg[t] = 1.f / (1.f + expf(-s));
}

// ---------------- MoE routing ----------------
__global__ void zero_cnt_kernel(int* cnt) { if (threadIdx.x < E) cnt[threadIdx.x] = 0; }

__global__ void routing_kernel(const float* __restrict__ logits, int* __restrict__ cnt,
                               int* __restrict__ tke, int* __restrict__ tks,
                               float* __restrict__ tkw) {
    int t = blockIdx.x * blockDim.x + threadIdx.x;
    if (t >= S) return;
    float p[E];
    float mx = -3.4e38f;
    #pragma unroll
    for (int e = 0; e < E; e++) { p[e] = logits[t * E + e]; mx = fmaxf(mx, p[e]); }
    float sum = 0.f;
    #pragma unroll
    for (int e = 0; e < E; e++) { p[e] = expf(p[e] - mx); sum += p[e]; }
    float inv = 1.f / sum;
    #pragma unroll
    for (int e = 0; e < E; e++) p[e] *= inv;
    int ids[TOPK]; float ws[TOPK]; float wsum = 0.f;
    #pragma unroll
    for (int k = 0; k < TOPK; k++) {
        float bv = -1.f; int bi = 0;
        #pragma unroll
        for (int e = 0; e < E; e++) if (p[e] > bv) { bv = p[e]; bi = e; }
        ids[k] = bi; ws[k] = bv; wsum += bv; p[bi] = -2.f;
    }
    float wi = 1.f / wsum;
    #pragma unroll
    for (int k = 0; k < TOPK; k++) {
        int slot = atomicAdd(&cnt[ids[k]], 1);
        tke[t * TOPK + k] = ids[k];
        tks[t * TOPK + k] = slot;
        tkw[t * TOPK + k] = ws[k] * wi;
    }
}

__global__ void gather_kernel(const float* __restrict__ h2, const int* __restrict__ tke,
                              const int* __restrict__ tks, float* __restrict__ hbuf) {
    int idx = blockIdx.x;
    int t = idx >> 2;
    int e = tke[idx], slot = tks[idx];
    const float4* src = reinterpret_cast<const float4*>(h2 + (long long)t * H);
    float4* dst = reinterpret_cast<float4*>(hbuf + ((long long)e * S + slot) * H);
    for (int i = threadIdx.x; i < H / 4; i += blockDim.x) dst[i] = src[i];
}

__global__ void silumul_expert_kernel(float* __restrict__ gbuf, const float* __restrict__ ubuf,
                                      const int* __restrict__ cnt) {
    int e = blockIdx.y, slot = blockIdx.x;
    if (slot >= cnt[e]) return;
    long long base = ((long long)e * S + slot) * IM;
    for (int i = threadIdx.x; i < IM; i += blockDim.x) {
        float x = gbuf[base + i];
        gbuf[base + i] = (x / (1.f + expf(-x))) * ubuf[base + i];
    }
}

__global__ void combine_kernel(const float* __restrict__ shrd, const float* __restrict__ sg,
                               const float* __restrict__ ybuf,
                               const int* __restrict__ tke, const int* __restrict__ tks,
                               const float* __restrict__ tkw, float* __restrict__ out) {
    int t = blockIdx.x;
    float g = sg[t];
    int e0 = tke[t*4+0], e1 = tke[t*4+1], e2 = tke[t*4+2], e3 = tke[t*4+3];
    int s0 = tks[t*4+0], s1 = tks[t*4+1], s2 = tks[t*4+2], s3 = tks[t*4+3];
    float w0 = tkw[t*4+0], w1 = tkw[t*4+1], w2 = tkw[t*4+2], w3 = tkw[t*4+3];
    const float* y0 = ybuf + ((long long)e0 * S + s0) * H;
    const float* y1 = ybuf + ((long long)e1 * S + s1) * H;
    const float* y2 = ybuf + ((long long)e2 * S + s2) * H;
    const float* y3 = ybuf + ((long long)e3 * S + s3) * H;
    const float* sh = shrd + (long long)t * H;
    float* o = out + (long long)t * H;
    for (int i = threadIdx.x; i < H; i += blockDim.x)
        o[i] = g * sh[i] + w0 * y0[i] + w1 * y1[i] + w2 * y2[i] + w3 * y3[i];
}

// ---------------- host orchestration ----------------
static inline void gemm(const float* A, const float* B, const float* bias, float* C,
                        int M, int N, int K, int lda, int ldb, int ldc,
                        long long sA, long long sB, long long sC,
                        float alpha, int transB, const int* mcnt, int batch) {
    dim3 grid((N + 127) / 128, (M + 127) / 128, batch);
    tgemm_kernel<<<grid, 256>>>(A, B, bias, C, M, N, K, lda, ldb, ldc,
                                sA, sB, sC, alpha, transB, mcnt);
}

extern "C" void kernel_launch(void* const* d_in, const int* in_sizes, int n_in,
                              void* d_out, int out_size) {
    const int*   positions = (const int*)  d_in[0];
    const float* hidden    = (const float*)d_in[1];
    const float* ln1       = (const float*)d_in[2];
    const float* ln2       = (const float*)d_in[3];
    const float* q_w       = (const float*)d_in[4];
    const float* q_b       = (const float*)d_in[5];
    const float* k_w       = (const float*)d_in[6];
    const float* k_b       = (const float*)d_in[7];
    const float* v_w       = (const float*)d_in[8];
    const float* v_b       = (const float*)d_in[9];
    const float* o_w       = (const float*)d_in[10];
    const float* router_w  = (const float*)d_in[11];
    const float* we_gate   = (const float*)d_in[12];
    const float* we_up     = (const float*)d_in[13];
    const float* we_down   = (const float*)d_in[14];
    const float* ws_gate   = (const float*)d_in[15];
    const float* ws_up     = (const float*)d_in[16];
    const float* ws_down   = (const float*)d_in[17];
    const float* wsg       = (const float*)d_in[18];
    float* out = (float*)d_out;

    float *h1, *q, *k, *v, *scores, *attn, *attno, *x2, *h2, *gs, *us, *shrd;
    float *logits, *sgv, *hbuf, *gbuf, *ubuf, *ybuf, *tkw;
    int *cnt, *tke, *tks;
    cudaGetSymbolAddress((void**)&h1,     g_h1);
    cudaGetSymbolAddress((void**)&q,      g_q);
    cudaGetSymbolAddress((void**)&k,      g_k);
    cudaGetSymbolAddress((void**)&v,      g_v);
    cudaGetSymbolAddress((void**)&scores, g_scores);
    cudaGetSymbolAddress((void**)&attn,   g_attn);
    cudaGetSymbolAddress((void**)&attno,  g_attno);
    cudaGetSymbolAddress((void**)&x2,     g_x2);
    cudaGetSymbolAddress((void**)&h2,     g_h2);
    cudaGetSymbolAddress((void**)&gs,     g_gs);
    cudaGetSymbolAddress((void**)&us,     g_us);
    cudaGetSymbolAddress((void**)&shrd,   g_shared);
    cudaGetSymbolAddress((void**)&logits, g_logits);
    cudaGetSymbolAddress((void**)&sgv,    g_sg);
    cudaGetSymbolAddress((void**)&cnt,    g_cnt);
    cudaGetSymbolAddress((void**)&tke,    g_tk_e);
    cudaGetSymbolAddress((void**)&tks,    g_tk_slot);
    cudaGetSymbolAddress((void**)&tkw,    g_tk_w);
    cudaGetSymbolAddress((void**)&hbuf,   g_hbuf);
    cudaGetSymbolAddress((void**)&gbuf,   g_gbuf);
    cudaGetSymbolAddress((void**)&ubuf,   g_ubuf);
    cudaGetSymbolAddress((void**)&ybuf,   g_ybuf);

    // --- pre-attention norm + QKV + RoPE ---
    rmsnorm_kernel<<<S, 256>>>(hidden, ln1, h1);
    gemm(h1, q_w, q_b, q, S, H, H, H, H, H, 0, 0, 0, 1.f, 0, nullptr, 1);
    gemm(h1, k_w, k_b, k, S, H, H, H, H, H, 0, 0, 0, 1.f, 0, nullptr, 1);
    gemm(h1, v_w, v_b, v, S, H, H, H, H, H, 0, 0, 0, 1.f, 0, nullptr, 1);
    rope_kernel<<<S, 1024>>>(positions, q, k);

    // --- attention ---
    gemm(q, k, nullptr, scores, S, S, HD, H, H, S,
         HD, HD, (long long)S * S, 0.08838834764831845f, 1, nullptr, NH);
    softmax_causal_kernel<<<dim3(S, NH), 256>>>(scores);
    gemm(scores, v, nullptr, attn, S, HD, S, S, H, H,
         (long long)S * S, HD, HD, 1.f, 0, nullptr, NH);
    gemm(attn, o_w, nullptr, attno, S, H, H, H, H, H, 0, 0, 0, 1.f, 0, nullptr, 1);
    add_kernel<<<(S * H + 255) / 256, 256>>>(attno, hidden, x2, S * H);

    // --- post-attention norm ---
    rmsnorm_kernel<<<S, 256>>>(x2, ln2, h2);

    // --- shared expert ---
    gemm(h2, ws_gate, nullptr, gs, S, IS, H, H, IS, IS, 0, 0, 0, 1.f, 0, nullptr, 1);
    gemm(h2, ws_up,   nullptr, us, S, IS, H, H, IS, IS, 0, 0, 0, 1.f, 0, nullptr, 1);
    silumul_kernel<<<(S * IS + 255) / 256, 256>>>(gs, us, S * IS);
    gemm(gs, ws_down, nullptr, shrd, S, H, IS, IS, H, H, 0, 0, 0, 1.f, 0, nullptr, 1);
    sgate_kernel<<<S, 256>>>(h2, wsg, sgv);

    // --- router + sparse expert dispatch ---
    gemm(h2, router_w, nullptr, logits, S, E, H, H, E, E, 0, 0, 0, 1.f, 0, nullptr, 1);
    zero_cnt_kernel<<<1, 32>>>(cnt);
    routing_kernel<<<(S + 255) / 256, 256>>>(logits, cnt, tke, tks, tkw);
    gather_kernel<<<S * TOPK, 256>>>(h2, tke, tks, hbuf);

    // --- expert MLPs ---
    gemm(hbuf, we_gate, nullptr, gbuf, S, IM, H, H, IM, IM,
         (long long)S * H, (long long)H * IM, (long long)S * IM, 1.f, 0, cnt, E);
    gemm(hbuf, we_up,   nullptr, ubuf, S, IM, H, H, IM, IM,
         (long long)S * H, (long long)H * IM, (long long)S * IM, 1.f, 0, cnt, E);
    silumul_expert_kernel<<<dim3(S, E), 256>>>(gbuf, ubuf, cnt);
    gemm(gbuf, we_down, nullptr, ybuf, S, H, IM, IM, H, H,
         (long long)S * IM, (long long)IM * H, (long long)S * H, 1.f, 0, cnt, E);

    // --- final combine ---
    combine_kernel<<<S, 256>>>(shrd, sgv, ybuf, tke, tks, tkw, out);
}

// round 3
// speedup vs baseline: 3.6182x; 1.0897x over previous
#include <cuda_runtime.h>
#include <math.h>
#include <stdint.h>

#define S   1024
#define H   2048
#define NH  16
#define HD  128
#define E   16
#define TOPK 4
#define IM  1408
#define IS  5632
#define EPS 1e-6f

// ---------------- scratch (device globals; no allocations allowed) ----------------
__device__ float g_h1[S*H];
__device__ float g_q[S*H];
__device__ float g_k[S*H];
__device__ float g_v[S*H];
__device__ float g_scores[NH*S*S];
__device__ float g_attn[S*H];
__device__ float g_x2[S*H];
__device__ float g_h2[S*H];
__device__ float g_gs[S*IS];
__device__ float g_us[S*IS];
__device__ float g_shared[S*H];
__device__ float g_logits[S*E];
__device__ float g_sg[S];
__device__ int   g_cnt[E];
__device__ int   g_tk_e[S*TOPK];
__device__ int   g_tk_slot[S*TOPK];
__device__ float g_tk_w[S*TOPK];
__device__ float g_hbuf[E*S*H];
__device__ float g_gbuf[E*S*IM];
__device__ float g_ubuf[E*S*IM];
__device__ float g_ybuf[E*S*H];
__device__ float g_part[8388608];   // split-K partials (33.5 MB), reused

// ---------------- block reductions ----------------
__device__ __forceinline__ float blockReduceSum(float v) {
    __shared__ float sh[33];
    int lane = threadIdx.x & 31, wid = threadIdx.x >> 5;
    #pragma unroll
    for (int o = 16; o; o >>= 1) v += __shfl_down_sync(0xffffffffu, v, o);
    if (lane == 0) sh[wid] = v;
    __syncthreads();
    int nw = (blockDim.x + 31) >> 5;
    float t = (threadIdx.x < nw) ? sh[threadIdx.x] : 0.f;
    if (wid == 0) {
        #pragma unroll
        for (int o = 16; o; o >>= 1) t += __shfl_down_sync(0xffffffffu, t, o);
        if (lane == 0) sh[32] = t;
    }
    __syncthreads();
    float r = sh[32];
    __syncthreads();
    return r;
}

__device__ __forceinline__ float blockReduceMax(float v) {
    __shared__ float sh[33];
    int lane = threadIdx.x & 31, wid = threadIdx.x >> 5;
    #pragma unroll
    for (int o = 16; o; o >>= 1) v = fmaxf(v, __shfl_down_sync(0xffffffffu, v, o));
    if (lane == 0) sh[wid] = v;
    __syncthreads();
    int nw = (blockDim.x + 31) >> 5;
    float t = (threadIdx.x < nw) ? sh[threadIdx.x] : -3.4e38f;
    if (wid == 0) {
        #pragma unroll
        for (int o = 16; o; o >>= 1) t = fmaxf(t, __shfl_down_sync(0xffffffffu, t, o));
        if (lane == 0) sh[32] = t;
    }
    __syncthreads();
    float r = sh[32];
    __syncthreads();
    return r;
}

// ---------------- TF32 tensor-core GEMM (multi-set, batched, split-K) ----------------
__device__ __forceinline__ uint32_t f2tf32(float f) {
    uint32_t r;
    asm("cvt.rna.tf32.f32 %0, %1;" : "=r"(r) : "f"(f));
    return r;
}

__device__ __forceinline__ void mma_tf32(float& d0, float& d1, float& d2, float& d3,
                                         uint32_t a0, uint32_t a1, uint32_t a2, uint32_t a3,
                                         uint32_t b0, uint32_t b1) {
    asm volatile(
        "mma.sync.aligned.m16n8k8.row.col.f32.tf32.tf32.f32 "
        "{%0,%1,%2,%3}, {%4,%5,%6,%7}, {%8,%9}, {%0,%1,%2,%3};"
        : "+f"(d0), "+f"(d1), "+f"(d2), "+f"(d3)
        : "r"(a0), "r"(a1), "r"(a2), "r"(a3), "r"(b0), "r"(b1));
}

#define LDA_SH 20
#define LDB_SH 136
#define STG_SZ (128 * LDA_SH)   // 2560 u32 per stage (covers both layouts)

struct GSet { const float* B; float* C; const float* bias; };
struct GSets { GSet s[3]; };

__device__ __forceinline__ void stage_load(
    float4* avr, float4* bvr, const float* Ab, const float* Bb,
    int m0, int n0, int M, int N, int kt, int lda, int ldb, int transB,
    int arow, int acq, int brow, int bn4)
{
    const float4 zf4 = make_float4(0.f, 0.f, 0.f, 0.f);
    #pragma unroll
    for (int p = 0; p < 2; p++) {
        int r = arow + p * 64;
        avr[p] = (m0 + r < M)
            ? *reinterpret_cast<const float4*>(&Ab[(long long)(m0 + r) * lda + kt + acq]) : zf4;
    }
    if (!transB) {
        #pragma unroll
        for (int p = 0; p < 2; p++) {
            int k = kt + brow + p * 8;
            bvr[p] = (n0 + bn4 < N)
                ? *reinterpret_cast<const float4*>(&Bb[(long long)k * ldb + n0 + bn4]) : zf4;
        }
    } else {
        #pragma unroll
        for (int p = 0; p < 2; p++) {
            int r = arow + p * 64;
            bvr[p] = (n0 + r < N)
                ? *reinterpret_cast<const float4*>(&Bb[(long long)(n0 + r) * ldb + kt + acq]) : zf4;
        }
    }
}

__device__ __forceinline__ void stage_store(
    uint32_t* As, uint32_t* Bs, const float4* avr, const float4* bvr,
    int transB, int arow, int acq, int brow, int bn4)
{
    #pragma unroll
    for (int p = 0; p < 2; p++) {
        int r = arow + p * 64;
        uint32_t* d = &As[r * LDA_SH + acq];
        d[0] = f2tf32(avr[p].x); d[1] = f2tf32(avr[p].y);
        d[2] = f2tf32(avr[p].z); d[3] = f2tf32(avr[p].w);
    }
    if (!transB) {
        #pragma unroll
        for (int p = 0; p < 2; p++) {
            int k = brow + p * 8;
            uint32_t* d = &Bs[k * LDB_SH + bn4];
            d[0] = f2tf32(bvr[p].x); d[1] = f2tf32(bvr[p].y);
            d[2] = f2tf32(bvr[p].z); d[3] = f2tf32(bvr[p].w);
        }
    } else {
        #pragma unroll
        for (int p = 0; p < 2; p++) {
            int r = arow + p * 64;
            uint32_t* d = &Bs[r * LDA_SH + acq];
            d[0] = f2tf32(bvr[p].x); d[1] = f2tf32(bvr[p].y);
            d[2] = f2tf32(bvr[p].z); d[3] = f2tf32(bvr[p].w);
        }
    }
}

// grid.z = nsets * inner * nsplit; z -> (set, ib, sp)
__global__ void __launch_bounds__(256, 2)
tgemm_kernel(const float* __restrict__ A, GSets sets,
             int M, int N, int K, int lda, int ldb, int ldc,
             long long sA, long long sB, long long sC,
             float alpha, int transB, const int* __restrict__ mcnt,
             int inner, int nsplit, int ksz,
             float* __restrict__ part, long long sSplit)
{
    const int z = blockIdx.z;
    const int sp  = z % nsplit;
    const int t   = z / nsplit;
    const int ib  = t % inner;
    const int set = t / inner;

    const int Mfull = M;
    if (mcnt) M = mcnt[ib];
    const int m0 = blockIdx.y * 128;
    if (m0 >= M) return;
    const int n0 = blockIdx.x * 128;

    const float* Ab = A + (long long)ib * sA;
    const float* Bb = sets.s[set].B + (long long)ib * sB;
    const float* bias = sets.s[set].bias;
    float* Cb;
    int ldcc;
    if (nsplit > 1) {
        Cb = part + (long long)sp * sSplit + (long long)ib * ((long long)Mfull * N);
        ldcc = N;
        bias = nullptr;
    } else {
        Cb = sets.s[set].C + (long long)ib * sC;
        ldcc = ldc;
    }

    const int kbeg = (nsplit > 1) ? sp * ksz : 0;
    const int kend = (nsplit > 1) ? kbeg + ksz : K;

    __shared__ uint32_t As[2][STG_SZ];
    __shared__ uint32_t Bs[2][STG_SZ];

    const int tid  = threadIdx.x;
    const int lane = tid & 31;
    const int warp = tid >> 5;
    const int wm   = (warp & 3) * 32;
    const int wn   = (warp >> 2) * 64;
    const int g    = lane >> 2;
    const int tg   = lane & 3;

    const int arow = tid >> 2;
    const int acq  = (tid & 3) * 4;
    const int brow = tid >> 5;
    const int bn4  = (tid & 31) * 4;

    float acc[2][8][4];
    #pragma unroll
    for (int i = 0; i < 2; i++)
        #pragma unroll
        for (int j = 0; j < 8; j++)
            #pragma unroll
            for (int c = 0; c < 4; c++) acc[i][j][c] = 0.f;

    float4 avr[2], bvr[2];

    // prologue: tile kbeg -> stage 0
    stage_load(avr, bvr, Ab, Bb, m0, n0, M, N, kbeg, lda, ldb, transB, arow, acq, brow, bn4);
    stage_store(As[0], Bs[0], avr, bvr, transB, arow, acq, brow, bn4);
    __syncthreads();

    int p = 0;
    for (int kt = kbeg; kt < kend; kt += 16) {
        const bool has_next = (kt + 16 < kend);
        if (has_next)
            stage_load(avr, bvr, Ab, Bb, m0, n0, M, N, kt + 16, lda, ldb, transB,
                       arow, acq, brow, bn4);

        const uint32_t* Asp = As[p];
        const uint32_t* Bsp = Bs[p];
        #pragma unroll
        for (int kk = 0; kk < 16; kk += 8) {
            uint32_t af[2][4];
            #pragma unroll
            for (int mt = 0; mt < 2; mt++) {
                const uint32_t* base = &Asp[(wm + mt * 16 + g) * LDA_SH + kk + tg];
                af[mt][0] = base[0];
                af[mt][1] = base[8 * LDA_SH];
                af[mt][2] = base[4];
                af[mt][3] = base[8 * LDA_SH + 4];
            }
            uint32_t bf[8][2];
            if (!transB) {
                #pragma unroll
                for (int nt = 0; nt < 8; nt++) {
                    int n = wn + nt * 8 + g;
                    bf[nt][0] = Bsp[(kk + tg) * LDB_SH + n];
                    bf[nt][1] = Bsp[(kk + tg + 4) * LDB_SH + n];
                }
            } else {
                #pragma unroll
                for (int nt = 0; nt < 8; nt++) {
                    int n = wn + nt * 8 + g;
                    bf[nt][0] = Bsp[n * LDA_SH + kk + tg];
                    bf[nt][1] = Bsp[n * LDA_SH + kk + tg + 4];
                }
            }
            #pragma unroll
            for (int mt = 0; mt < 2; mt++)
                #pragma unroll
                for (int nt = 0; nt < 8; nt++)
                    mma_tf32(acc[mt][nt][0], acc[mt][nt][1], acc[mt][nt][2], acc[mt][nt][3],
                             af[mt][0], af[mt][1], af[mt][2], af[mt][3],
                             bf[nt][0], bf[nt][1]);
        }

        if (has_next) {
            stage_store(As[1 - p], Bs[1 - p], avr, bvr, transB, arow, acq, brow, bn4);
            __syncthreads();
            p ^= 1;
        }
    }

    // epilogue
    #pragma unroll
    for (int mt = 0; mt < 2; mt++) {
        int r0 = m0 + wm + mt * 16 + g;
        int r1 = r0 + 8;
        #pragma unroll
        for (int nt = 0; nt < 8; nt++) {
            int col = n0 + wn + nt * 8 + 2 * tg;
            if (col >= N) continue;
            float b0 = bias ? bias[col]     : 0.f;
            float b1 = bias ? bias[col + 1] : 0.f;
            if (r0 < M) {
                float2 v = make_float2(acc[mt][nt][0] * alpha + b0,
                                       acc[mt][nt][1] * alpha + b1);
                *reinterpret_cast<float2*>(&Cb[(long long)r0 * ldcc + col]) = v;
            }
            if (r1 < M) {
                float2 v = make_float2(acc[mt][nt][2] * alpha + b0,
                                       acc[mt][nt][3] * alpha + b1);
                *reinterpret_cast<float2*>(&Cb[(long long)r1 * ldcc + col]) = v;
            }
        }
    }
}

// sum split-K partials -> final C (optionally + bias + addend)
__global__ void reduce_split_kernel(const float* __restrict__ P, float* __restrict__ C,
                                    const float* __restrict__ bias, const float* __restrict__ addend,
                                    int nsplit, long long sSplit, long long pBatch,
                                    int M, int N, int ldc, long long sC)
{
    int b = blockIdx.y;
    long long total = (long long)M * N;
    for (long long idx = (long long)blockIdx.x * blockDim.x + threadIdx.x; idx < total;
         idx += (long long)gridDim.x * blockDim.x) {
        int m = (int)(idx / N), n = (int)(idx % N);
        float s = 0.f;
        for (int sp = 0; sp < nsplit; sp++)
            s += P[(long long)sp * sSplit + (long long)b * pBatch + idx];
        long long o = (long long)b * sC + (long long)m * ldc + n;
        if (bias)   s += bias[n];
        if (addend) s += addend[o];
        C[o] = s;
    }
}

// ---------------- elementwise / norm / attention helpers ----------------
__global__ void rmsnorm_kernel(const float* __restrict__ x, const float* __restrict__ w,
                               float* __restrict__ y) {
    int t = blockIdx.x;
    const float* xr = x + (long long)t * H;
    float s = 0.f;
    for (int i = threadIdx.x; i < H; i += blockDim.x) { float v = xr[i]; s += v * v; }
    s = blockReduceSum(s);
    float scale = rsqrtf(s / (float)H + EPS);
    float* yr = y + (long long)t * H;
    for (int i = threadIdx.x; i < H; i += blockDim.x) yr[i] = xr[i] * scale * w[i];
}

__global__ void rope_kernel(const int* __restrict__ pos, float* __restrict__ q,
                            float* __restrict__ k) {
    int t = blockIdx.x;
    int h = threadIdx.x >> 6;
    int d = threadIdx.x & 63;
    float p = (float)pos[t];
    float inv = powf(1.0e6f, -(float)d * (1.0f / 64.0f));
    float ang = p * inv;
    float sn, cs;
    sincosf(ang, &sn, &cs);
    long long base = (long long)t * H + h * HD;
    float x1 = q[base + d], x2 = q[base + 64 + d];
    q[base + d]      = x1 * cs - x2 * sn;
    q[base + 64 + d] = x2 * cs + x1 * sn;
    x1 = k[base + d]; x2 = k[base + 64 + d];
    k[base + d]      = x1 * cs - x2 * sn;
    k[base + 64 + d] = x2 * cs + x1 * sn;
}

__global__ void softmax_causal_kernel(float* __restrict__ scores) {
    int r = blockIdx.x, h = blockIdx.y;
    float* row = scores + ((long long)h * S + r) * (long long)S;
    int len = r + 1;
    float m = -3.4e38f;
    for (int i = threadIdx.x; i < len; i += blockDim.x) m = fmaxf(m, row[i]);
    m = blockReduceMax(m);
    float s = 0.f;
    for (int i = threadIdx.x; i < len; i += blockDim.x) {
        float e = expf(row[i] - m);
        row[i] = e; s += e;
    }
    s = blockReduceSum(s);
    float inv = 1.f / s;
    for (int i = threadIdx.x; i < len; i += blockDim.x) row[i] *= inv;
    for (int i = len + threadIdx.x; i < S; i += blockDim.x) row[i] = 0.f;
}

__global__ void silumul_kernel(float* __restrict__ g, const float* __restrict__ u, int n) {
    int i = blockIdx.x * blockDim.x + threadIdx.x;
    if (i < n) { float x = g[i]; g[i] = (x / (1.f + expf(-x))) * u[i]; }
}

__global__ void sgate_kernel(const float* __restrict__ h2, const float* __restrict__ wsg,
                             float* __restrict__ sg) {
    int t = blockIdx.x;
    float s = 0.f;
    for (int i = threadIdx.x; i < H; i += blockDim.x) s += h2[(long long)t * H + i] * wsg[i];
    s = blockReduceSum(s);
    if (threadIdx.x == 0) sg[t] = 1.f / (1.f + expf(-s));
}

// ---------------- MoE routing ----------------
__global__ void zero_cnt_kernel(int* cnt) { if (threadIdx.x < E) cnt[threadIdx.x] = 0; }

__global__ void routing_kernel(const float* __restrict__ logits, int* __restrict__ cnt,
                               int* __restrict__ tke, int* __restrict__ tks,
                               float* __restrict__ tkw) {
    int t = blockIdx.x * blockDim.x + threadIdx.x;
    if (t >= S) return;
    float p[E];
    float mx = -3.4e38f;
    #pragma unroll
    for (int e = 0; e < E; e++) { p[e] = logits[t * E + e]; mx = fmaxf(mx, p[e]); }
    float sum = 0.f;
    #pragma unroll
    for (int e = 0; e < E; e++) { p[e] = expf(p[e] - mx); sum += p[e]; }
    float inv = 1.f / sum;
    #pragma unroll
    for (int e = 0; e < E; e++) p[e] *= inv;
    int ids[TOPK]; float ws[TOPK]; float wsum = 0.f;
    #pragma unroll
    for (int k = 0; k < TOPK; k++) {
        float bv = -1.f; int bi = 0;
        #pragma unroll
        for (int e = 0; e < E; e++) if (p[e] > bv) { bv = p[e]; bi = e; }
        ids[k] = bi; ws[k] = bv; wsum += bv; p[bi] = -2.f;
    }
    float wi = 1.f / wsum;
    #pragma unroll
    for (int k = 0; k < TOPK; k++) {
        int slot = atomicAdd(&cnt[ids[k]], 1);
        tke[t * TOPK + k] = ids[k];
        tks[t * TOPK + k] = slot;
        tkw[t * TOPK + k] = ws[k] * wi;
    }
}

__global__ void gather_kernel(const float* __restrict__ h2, const int* __restrict__ tke,
                              const int* __restrict__ tks, float* __restrict__ hbuf) {
    int idx = blockIdx.x;
    int t = idx >> 2;
    int e = tke[idx], slot = tks[idx];
    const float4* src = reinterpret_cast<const float4*>(h2 + (long long)t * H);
    float4* dst = reinterpret_cast<float4*>(hbuf + ((long long)e * S + slot) * H);
    for (int i = threadIdx.x; i < H / 4; i += blockDim.x) dst[i] = src[i];
}

__global__ void silumul_expert_kernel(float* __restrict__ gbuf, const float* __restrict__ ubuf,
                                      const int* __restrict__ cnt) {
    int e = blockIdx.y, slot = blockIdx.x;
    if (slot >= cnt[e]) return;
    long long base = ((long long)e * S + slot) * IM;
    for (int i = threadIdx.x; i < IM; i += blockDim.x) {
        float x = gbuf[base + i];
        gbuf[base + i] = (x / (1.f + expf(-x))) * ubuf[base + i];
    }
}

__global__ void combine_kernel(const float* __restrict__ shrd, const float* __restrict__ sg,
                               const float* __restrict__ ybuf,
                               const int* __restrict__ tke, const int* __restrict__ tks,
                               const float* __restrict__ tkw, float* __restrict__ out) {
    int t = blockIdx.x;
    float g = sg[t];
    int e0 = tke[t*4+0], e1 = tke[t*4+1], e2 = tke[t*4+2], e3 = tke[t*4+3];
    int s0 = tks[t*4+0], s1 = tks[t*4+1], s2 = tks[t*4+2], s3 = tks[t*4+3];
    float w0 = tkw[t*4+0], w1 = tkw[t*4+1], w2 = tkw[t*4+2], w3 = tkw[t*4+3];
    const float* y0 = ybuf + ((long long)e0 * S + s0) * H;
    const float* y1 = ybuf + ((long long)e1 * S + s1) * H;
    const float* y2 = ybuf + ((long long)e2 * S + s2) * H;
    const float* y3 = ybuf + ((long long)e3 * S + s3) * H;
    const float* sh = shrd + (long long)t * H;
    float* o = out + (long long)t * H;
    for (int i = threadIdx.x; i < H; i += blockDim.x)
        o[i] = g * sh[i] + w0 * y0[i] + w1 * y1[i] + w2 * y2[i] + w3 * y3[i];
}

// ---------------- host orchestration ----------------
static inline void gemm_multi(const float* A, const GSets& sets, int nsets,
                              int M, int N, int K, int lda, int ldb, int ldc,
                              long long sA, long long sB, long long sC,
                              float alpha, int transB, const int* mcnt, int inner,
                              int nsplit = 1, int ksz = 0, float* part = nullptr,
                              long long sSplit = 0) {
    dim3 grid((N + 127) / 128, (M + 127) / 128, nsets * inner * nsplit);
    tgemm_kernel<<<grid, 256>>>(A, sets, M, N, K, lda, ldb, ldc, sA, sB, sC,
                                alpha, transB, mcnt, inner, nsplit, ksz, part, sSplit);
}

static inline void gemm1(const float* A, const float* B, const float* bias, float* C,
                         int M, int N, int K, int lda, int ldb, int ldc,
                         long long sA, long long sB, long long sC,
                         float alpha, int transB, const int* mcnt, int inner) {
    GSets s{}; s.s[0] = {B, C, bias};
    gemm_multi(A, s, 1, M, N, K, lda, ldb, ldc, sA, sB, sC, alpha, transB, mcnt, inner);
}

extern "C" void kernel_launch(void* const* d_in, const int* in_sizes, int n_in,
                              void* d_out, int out_size) {
    const int*   positions = (const int*)  d_in[0];
    const float* hidden    = (const float*)d_in[1];
    const float* ln1       = (const float*)d_in[2];
    const float* ln2       = (const float*)d_in[3];
    const float* q_w       = (const float*)d_in[4];
    const float* q_b       = (const float*)d_in[5];
    const float* k_w       = (const float*)d_in[6];
    const float* k_b       = (const float*)d_in[7];
    const float* v_w       = (const float*)d_in[8];
    const float* v_b       = (const float*)d_in[9];
    const float* o_w       = (const float*)d_in[10];
    const float* router_w  = (const float*)d_in[11];
    const float* we_gate   = (const float*)d_in[12];
    const float* we_up     = (const float*)d_in[13];
    const float* we_down   = (const float*)d_in[14];
    const float* ws_gate   = (const float*)d_in[15];
    const float* ws_up     = (const float*)d_in[16];
    const float* ws_down   = (const float*)d_in[17];
    const float* wsg       = (const float*)d_in[18];
    float* out = (float*)d_out;

    float *h1, *q, *k, *v, *scores, *attn, *x2, *h2, *gs, *us, *shrd;
    float *logits, *sgv, *hbuf, *gbuf, *ubuf, *ybuf, *tkw, *part;
    int *cnt, *tke, *tks;
    cudaGetSymbolAddress((void**)&h1,     g_h1);
    cudaGetSymbolAddress((void**)&q,      g_q);
    cudaGetSymbolAddress((void**)&k,      g_k);
    cudaGetSymbolAddress((void**)&v,      g_v);
    cudaGetSymbolAddress((void**)&scores, g_scores);
    cudaGetSymbolAddress((void**)&attn,   g_attn);
    cudaGetSymbolAddress((void**)&x2,     g_x2);
    cudaGetSymbolAddress((void**)&h2,     g_h2);
    cudaGetSymbolAddress((void**)&gs,     g_gs);
    cudaGetSymbolAddress((void**)&us,     g_us);
    cudaGetSymbolAddress((void**)&shrd,   g_shared);
    cudaGetSymbolAddress((void**)&logits, g_logits);
    cudaGetSymbolAddress((void**)&sgv,    g_sg);
    cudaGetSymbolAddress((void**)&cnt,    g_cnt);
    cudaGetSymbolAddress((void**)&tke,    g_tk_e);
    cudaGetSymbolAddress((void**)&tks,    g_tk_slot);
    cudaGetSymbolAddress((void**)&tkw,    g_tk_w);
    cudaGetSymbolAddress((void**)&hbuf,   g_hbuf);
    cudaGetSymbolAddress((void**)&gbuf,   g_gbuf);
    cudaGetSymbolAddress((void**)&ubuf,   g_ubuf);
    cudaGetSymbolAddress((void**)&ybuf,   g_ybuf);
    cudaGetSymbolAddress((void**)&part,   g_part);

    // --- pre-attention norm + fused QKV + RoPE ---
    rmsnorm_kernel<<<S, 256>>>(hidden, ln1, h1);
    {
        GSets s{};
        s.s[0] = {q_w, q, q_b};
        s.s[1] = {k_w, k, k_b};
        s.s[2] = {v_w, v, v_b};
        gemm_multi(h1, s, 3, S, H, H, H, H, H, 0, 0, 0, 1.f, 0, nullptr, 1);
    }
    rope_kernel<<<S, 1024>>>(positions, q, k);

    // --- attention scores + softmax ---
    gemm1(q, k, nullptr, scores, S, S, HD, H, H, S,
          HD, HD, (long long)S * S, 0.08838834764831845f, 1, nullptr, NH);
    softmax_causal_kernel<<<dim3(S, NH), 256>>>(scores);

    // --- PV (split-K 4) ---
    {
        GSets s{}; s.s[0] = {v, nullptr, nullptr};
        long long sSplit = (long long)NH * S * HD;
        gemm_multi(scores, s, 1, S, HD, S, S, H, 0,
                   (long long)S * S, HD, 0, 1.f, 0, nullptr, NH, 4, 256, part, sSplit);
        reduce_split_kernel<<<dim3((S * HD + 255) / 256, NH), 256>>>(
            part, attn, nullptr, nullptr, 4, sSplit, (long long)S * HD, S, HD, H, HD);
    }

    // --- O proj (split-K 2, residual fused into reduce) ---
    {
        GSets s{}; s.s[0] = {o_w, nullptr, nullptr};
        long long sSplit = (long long)S * H;
        gemm_multi(attn, s, 1, S, H, H, H, H, 0, 0, 0, 0,
                   1.f, 0, nullptr, 1, 2, 1024, part, sSplit);
        reduce_split_kernel<<<dim3((S * H + 255) / 256, 1), 256>>>(
            part, x2, nullptr, hidden, 2, sSplit, 0, S, H, H, 0);
    }

    rmsnorm_kernel<<<S, 256>>>(x2, ln2, h2);

    // --- shared expert: fused gate/up, split-K down ---
    {
        GSets s{};
        s.s[0] = {ws_gate, gs, nullptr};
        s.s[1] = {ws_up,   us, nullptr};
        gemm_multi(h2, s, 2, S, IS, H, H, IS, IS, 0, 0, 0, 1.f, 0, nullptr, 1);
    }
    silumul_kernel<<<(S * IS + 255) / 256, 256>>>(gs, us, S * IS);
    {
        GSets s{}; s.s[0] = {ws_down, nullptr, nullptr};
        long long sSplit = (long long)S * H;
        gemm_multi(gs, s, 1, S, H, IS, IS, H, 0, 0, 0, 0,
                   1.f, 0, nullptr, 1, 2, 2816, part, sSplit);
        reduce_split_kernel<<<dim3((S * H + 255) / 256, 1), 256>>>(
            part, shrd, nullptr, nullptr, 2, sSplit, 0, S, H, H, 0);
    }
    sgate_kernel<<<S, 256>>>(h2, wsg, sgv);

    // --- router + dispatch ---
    gemm1(h2, router_w, nullptr, logits, S, E, H, H, E, E, 0, 0, 0, 1.f, 0, nullptr, 1);
    zero_cnt_kernel<<<1, 32>>>(cnt);
    routing_kernel<<<(S + 255) / 256, 256>>>(logits, cnt, tke, tks, tkw);
    gather_kernel<<<S * TOPK, 256>>>(h2, tke, tks, hbuf);

    // --- expert MLPs: fused gate/up (z=32), down ---
    {
        GSets s{};
        s.s[0] = {we_gate, gbuf, nullptr};
        s.s[1] = {we_up,   ubuf, nullptr};
        gemm_multi(hbuf, s, 2, S, IM, H, H, IM, IM,
                   (long long)S * H, (long long)H * IM, (long long)S * IM,
                   1.f, 0, cnt, E);
    }
    silumul_expert_kernel<<<dim3(S, E), 256>>>(gbuf, ubuf, cnt);
    gemm1(gbuf, we_down, nullptr, ybuf, S, H, IM, IM, H, H,
          (long long)S * IM, (long long)IM * H, (long long)S * H, 1.f, 0, cnt, E);

    // --- final combine ---
    combine_kernel<<<S, 256>>>(shrd, sgv, ybuf, tke, tks, tkw, out);
}